// round 17
// baseline (speedup 1.0000x reference)
#include <cuda_runtime.h>
#include <cuda_bf16.h>
#include <cstdint>

#define BB 2
#define NN 8192
#define KK 16
#define CIN 64
#define COUT 128
#define NPTS (BB*NN)

// smem offsets (bytes) -- 4 points/CTA, ~104 KB => 2 CTAs/SM
#define OFF_X    0          // A frags: 4 pts x (hi 4KB | lo 4KB) = 32 KB (reused as Wo partials)
#define OFF_Y    32768      // PE frags, same layout, 32 KB
#define OFF_B    65536      // single 32 KB chunk buffer = {Whi half, Wlo half}
#define OFF_AGG  98304      // 4 x 128 fp32
#define OFF_Q    100352     // 4 x 128 fp32
#define OFF_W1   102400     // Wp1(384)+bp1(128) fp32
#define OFF_IDX  104448     // 64 int
#define SMEM_TOTAL 104704

__device__ float g_q[NPTS * COUT];
__device__ float g_k[NPTS * COUT];
__device__ float g_v[NPTS * COUT];
// 3 stages x 2 k-half chunks; chunk = {Whi 64 k-rows (16KB) | Wlo same rows (16KB)}
__device__ __align__(16) uint16_t g_Bpk[3 * 2 * 16384];

// ---------------- mma.sync (family-common PTX) ----------------
__device__ __forceinline__ void mma16816(float* c, uint32_t a0, uint32_t a1,
                                         uint32_t a2, uint32_t a3,
                                         uint32_t b0, uint32_t b1) {
    asm volatile(
        "mma.sync.aligned.m16n8k16.row.col.f32.bf16.bf16.f32 "
        "{%0,%1,%2,%3}, {%4,%5,%6,%7}, {%8,%9}, {%0,%1,%2,%3};"
        : "+f"(c[0]), "+f"(c[1]), "+f"(c[2]), "+f"(c[3])
        : "r"(a0), "r"(a1), "r"(a2), "r"(a3), "r"(b0), "r"(b1));
}

// fused 3-term half-pass: 2 points x 32-col quarter over one K-half (64 rows).
__device__ __forceinline__ void mma_pass_half(float* acc0, float* acc1,
                                              const char* xb0, const char* xb1,
                                              const uint4* __restrict__ sB,
                                              int h, int lane, int half) {
    #pragma unroll
    for (int kkm = 0; kkm < 4; ++kkm) {
        int ko = (half * 4 + kkm) * 512 + lane * 16;
        uint4 A0h = *(const uint4*)(xb0 + ko);
        uint4 A0l = *(const uint4*)(xb0 + 4096 + ko);
        uint4 A1h = *(const uint4*)(xb1 + ko);
        uint4 A1l = *(const uint4*)(xb1 + 4096 + ko);
        #pragma unroll
        for (int jj = 0; jj < 2; ++jj) {
            int bi = kkm*256 + (2*h + jj)*32 + lane;
            uint4 bh = sB[bi];
            uint4 bl = sB[1024 + bi];         // Wlo half is +16KB
            float* a0 = acc0 + jj*8;
            float* a1 = acc1 + jj*8;
            mma16816(a0,     A0h.x, A0h.y, A0h.z, A0h.w, bh.x, bh.y);
            mma16816(a0 + 4, A0h.x, A0h.y, A0h.z, A0h.w, bh.z, bh.w);
            mma16816(a1,     A1h.x, A1h.y, A1h.z, A1h.w, bh.x, bh.y);
            mma16816(a1 + 4, A1h.x, A1h.y, A1h.z, A1h.w, bh.z, bh.w);
            mma16816(a0,     A0l.x, A0l.y, A0l.z, A0l.w, bh.x, bh.y);
            mma16816(a0 + 4, A0l.x, A0l.y, A0l.z, A0l.w, bh.z, bh.w);
            mma16816(a1,     A1l.x, A1l.y, A1l.z, A1l.w, bh.x, bh.y);
            mma16816(a1 + 4, A1l.x, A1l.y, A1l.z, A1l.w, bh.z, bh.w);
            mma16816(a0,     A0h.x, A0h.y, A0h.z, A0h.w, bl.x, bl.y);
            mma16816(a0 + 4, A0h.x, A0h.y, A0h.z, A0h.w, bl.z, bl.w);
            mma16816(a1,     A1h.x, A1h.y, A1h.z, A1h.w, bl.x, bl.y);
            mma16816(a1 + 4, A1h.x, A1h.y, A1h.z, A1h.w, bl.z, bl.w);
        }
    }
}

// pack an (even,odd) col pair into truncated-hi bf16x2 + rounded-lo bf16x2
__device__ __forceinline__ void pack_hilo(float v0, float v1, uint32_t& hi, uint32_t& lo) {
    hi = __byte_perm(__float_as_uint(v0), __float_as_uint(v1), 0x7632);
    float l0 = v0 - __uint_as_float(__float_as_uint(v0) & 0xFFFF0000u);
    float l1 = v1 - __uint_as_float(__float_as_uint(v1) & 0xFFFF0000u);
    asm("cvt.rn.bf16x2.f32 %0, %1, %2;" : "=r"(lo) : "f"(l1), "f"(l0));
}

// batched fragment store: one STS.128 (hi) + one STS.128 (lo) per kkm-pair j.
// a8 = acc + 8*j : words = {g2=2j:(rr0,rr1), g2=2j+1:(rr0,rr1)} — identical layout
// to the old per-word stores, now conflict-free.
__device__ __forceinline__ void frag_store_quad(char* base, int h, int j, int lane,
                                                const float* a8) {
    uint4 H, L;
    pack_hilo(a8[0], a8[1], H.x, L.x);
    pack_hilo(a8[2], a8[3], H.y, L.y);
    pack_hilo(a8[4], a8[5], H.z, L.z);
    pack_hilo(a8[6], a8[7], H.w, L.w);
    int off = (2*h + j) * 512 + lane * 16;
    *(uint4*)(base + off) = H;
    *(uint4*)(base + 4096 + off) = L;
}

__device__ __forceinline__ void init_bias_h(float* acc, const float* __restrict__ bias,
                                            int h, int lane) {
    int cb = 32*h + (lane & 3) * 2;
    #pragma unroll
    for (int g2 = 0; g2 < 4; ++g2) {
        float2 b2 = *(const float2*)(bias + cb + g2*8);
        acc[g2*4+0] = b2.x; acc[g2*4+1] = b2.y; acc[g2*4+2] = b2.x; acc[g2*4+3] = b2.y;
    }
}

__device__ __forceinline__ float blo(uint32_t u) { return __uint_as_float(u << 16); }
__device__ __forceinline__ float bhi(uint32_t u) { return __uint_as_float(u & 0xFFFF0000u); }

// 32 KB chunk prefetch gmem -> smem (256 threads)
__device__ __forceinline__ void prefetch32(char* sbuf, const uint16_t* __restrict__ gsrc,
                                           int tid) {
    uint32_t sa = (uint32_t)__cvta_generic_to_shared(sbuf) + tid * 16;
    const char* gp = (const char*)gsrc + tid * 16;
    #pragma unroll
    for (int i = 0; i < 8; ++i)
        asm volatile("cp.async.cg.shared.global [%0], [%1], 16;"
                     :: "r"(sa + i * 4096), "l"(gp + i * 4096));
    asm volatile("cp.async.commit_group;" ::: "memory");
}
#define CP_WAIT_ALL() asm volatile("cp.async.wait_group 0;" ::: "memory")

// ---------------- kernel 0: fused prep = weight pack + q/k/v projections -------
__global__ void __launch_bounds__(256) prep_kernel(
    const float* __restrict__ x,
    const float* __restrict__ Wq,  const float* __restrict__ bq,
    const float* __restrict__ Wkv, const float* __restrict__ bkv,
    const float* __restrict__ Wp2, const float* __restrict__ Wa1,
    const float* __restrict__ Wa2)
{
    __shared__ float s_x[32][64];
    const int tid = threadIdx.x;

    if (blockIdx.x < 384) {        // ---- pack weights: per-k-half {hi|lo} chunks ----
        int t = blockIdx.x * 256 + tid;          // < 98304
        int s = t / 32768, e = t % 32768;
        int r = e >> 14, e2 = e & 16383;         // r: 0=hi, 1=lo
        int kp = e2 >> 7, n = e2 & 127;
        const float* W = (s == 0) ? Wp2 : (s == 1) ? Wa1 : Wa2;
        float w = W[kp * 128 + n];
        uint32_t wu = __float_as_uint(w);
        uint16_t val;
        if (r == 0) val = (uint16_t)(wu >> 16);
        else {
            float lo = w - __uint_as_float(wu & 0xFFFF0000u);
            val = __bfloat16_as_ushort(__float2bfloat16(lo));
        }
        int c   = kp >> 6;                       // k-half chunk
        int kkl = (kp >> 4) & 3;                 // local k16 index within half
        int row = kp & 15;
        int reg = row >> 3, half = row & 1, l = ((n & 7) << 2) | ((row >> 1) & 3);
        int p = n >> 4, jo = (n >> 3) & 1;
        int fragoff = p * 512 + l * 16 + jo * 8 + reg * 4 + half * 2;
        g_Bpk[(s * 2 + c) * 16384 + r * 8192 + kkl * 2048 + (fragoff >> 1)] = val;
        return;
    }

    // ---- projections: 32 rows x 128 cols per block ----
    int pb = blockIdx.x - 384;
    const int g = pb >> 9;                 // 0:q 1:k 2:v
    const int row0 = (pb & 511) * 32;

    for (int i = tid; i < 512; i += 256) {
        int r = i >> 4, c4 = i & 15;
        reinterpret_cast<float4*>(&s_x[r][0])[c4] =
            reinterpret_cast<const float4*>(x + (size_t)(row0 + r) * CIN)[c4];
    }
    __syncthreads();

    const int rt = tid >> 5, l = tid & 31;
    const float* W; const float* bias; float* out; int ldw, cb;
    if (g == 0)      { W = Wq;  ldw = 128; cb = 0;   bias = bq;        out = g_q; }
    else if (g == 1) { W = Wkv; ldw = 256; cb = 0;   bias = bkv;       out = g_k; }
    else             { W = Wkv; ldw = 256; cb = 128; bias = bkv + 128; out = g_v; }

    float4 acc[4];
    #pragma unroll
    for (int r = 0; r < 4; ++r) acc[r] = make_float4(0.f, 0.f, 0.f, 0.f);
    const float* wp = W + cb + 4 * l;
    #pragma unroll 4
    for (int k = 0; k < CIN; ++k) {
        float4 w = *reinterpret_cast<const float4*>(wp + (size_t)k * ldw);
        #pragma unroll
        for (int r = 0; r < 4; ++r) {
            float a = s_x[rt * 4 + r][k];
            acc[r].x = fmaf(a, w.x, acc[r].x); acc[r].y = fmaf(a, w.y, acc[r].y);
            acc[r].z = fmaf(a, w.z, acc[r].z); acc[r].w = fmaf(a, w.w, acc[r].w);
        }
    }
    float4 bv = *reinterpret_cast<const float4*>(bias + 4 * l);
    #pragma unroll
    for (int r = 0; r < 4; ++r) {
        float4 o = acc[r];
        o.x += bv.x; o.y += bv.y; o.z += bv.z; o.w += bv.w;
        *reinterpret_cast<float4*>(out + (size_t)(row0 + rt * 4 + r) * COUT + 4 * l) = o;
    }
}

// ---------------- kernel 1: fused attention, 4 pts/CTA, 8 warps, 2 CTAs/SM ----
__global__ void __launch_bounds__(256, 2) attn_kernel(
    const float* __restrict__ pos, const int* __restrict__ idx,
    const float* __restrict__ Wp1, const float* __restrict__ bp1,
    const float* __restrict__ bp2, const float* __restrict__ ba1,
    const float* __restrict__ ba2,
    const float* __restrict__ Wo,  const float* __restrict__ bo,
    float* __restrict__ out)
{
    extern __shared__ char smem[];
    char*  bufX = smem + OFF_X;
    char*  bufY = smem + OFF_Y;
    uint4* sB   = (uint4*)(smem + OFF_B);
    float* sAgg = (float*)(smem + OFF_AGG);
    float* sQ   = (float*)(smem + OFF_Q);
    float* sW1  = (float*)(smem + OFF_W1);
    int*   sIdx = (int*)  (smem + OFF_IDX);

    const int tid = threadIdx.x, w = tid >> 5, lane = tid & 31;
    const int q = w & 1, h = w >> 1;            // points 2q,2q+1; col-quarter h (0..3)
    const int p0 = blockIdx.x * 4;
    const int bbase = (p0 / NN) * NN;
    const int r0 = lane >> 2;
    const int cl = (lane & 3) * 2;

    char* xb0 = bufX + (2*q)     * 8192;
    char* xb1 = bufX + (2*q + 1) * 8192;
    char* yb0 = bufY + (2*q)     * 8192;
    char* yb1 = bufY + (2*q + 1) * 8192;

    prefetch32(smem + OFF_B, g_Bpk, tid);        // s0 chunk0

    if (tid < 64) sIdx[tid] = idx[p0 * KK + tid];
    for (int i = tid; i < 512; i += 256) sW1[i] = (i < 384) ? Wp1[i] : bp1[i - 384];
    if (tid < 128) ((float4*)sQ)[tid] = ((const float4*)(g_q + (size_t)p0 * COUT))[tid];
    __syncthreads();                             // idx/W1/Q visible

    const int i00 = sIdx[(2*q)*16 + r0],     i01 = sIdx[(2*q)*16 + r0 + 8];
    const int i10 = sIdx[(2*q+1)*16 + r0],   i11 = sIdx[(2*q+1)*16 + r0 + 8];

    float acc0[16], acc1[16];

    // ---- stage 1 (scalar): hidden = relu(pos_diff @ Wp1 + bp1) -> bufX frags ----
    {
        float pdx[2][2], pdy[2][2], pdz[2][2];
        #pragma unroll
        for (int pt = 0; pt < 2; ++pt) {
            const float* pp = pos + (size_t)(p0 + 2*q + pt) * 3;
            float px = pp[0], py = pp[1], pz = pp[2];
            #pragma unroll
            for (int rr = 0; rr < 2; ++rr) {
                int nb = pt ? (rr ? i11 : i10) : (rr ? i01 : i00);
                const float* pn = pos + (size_t)(bbase + nb) * 3;
                pdx[pt][rr] = px - pn[0]; pdy[pt][rr] = py - pn[1]; pdz[pt][rr] = pz - pn[2];
            }
        }
        #pragma unroll
        for (int pt = 0; pt < 2; ++pt) {
            char* xb = pt ? xb1 : xb0;
            #pragma unroll
            for (int j = 0; j < 2; ++j) {
                float a8[8];
                #pragma unroll
                for (int gg = 0; gg < 2; ++gg) {
                    int c = 32*h + (2*j + gg)*8 + cl;
                    #pragma unroll
                    for (int rr = 0; rr < 2; ++rr) {
                        float v0 = fmaf(pdx[pt][rr], sW1[c],
                                   fmaf(pdy[pt][rr], sW1[128 + c],
                                   fmaf(pdz[pt][rr], sW1[256 + c], sW1[384 + c])));
                        float v1 = fmaf(pdx[pt][rr], sW1[c + 1],
                                   fmaf(pdy[pt][rr], sW1[128 + c + 1],
                                   fmaf(pdz[pt][rr], sW1[256 + c + 1], sW1[384 + c + 1])));
                        a8[gg*4 + rr*2 + 0] = fmaxf(v0, 0.f);
                        a8[gg*4 + rr*2 + 1] = fmaxf(v1, 0.f);
                    }
                }
                frag_store_quad(xb, h, j, lane, a8);
            }
        }
    }
    CP_WAIT_ALL(); __syncthreads();              // B = s0 chunk0; frags visible

    // ================= stage 0: pos_enc = hidden @ Wp2 + bp2 =================
    init_bias_h(acc0, bp2, h, lane); init_bias_h(acc1, bp2, h, lane);
    mma_pass_half(acc0, acc1, xb0, xb1, sB, h, lane, 0);
    __syncthreads();
    prefetch32(smem + OFF_B, g_Bpk + 1 * 16384, tid);    // s0 chunk1
    CP_WAIT_ALL(); __syncthreads();
    mma_pass_half(acc0, acc1, xb0, xb1, sB, h, lane, 1);
    __syncthreads();                                      // B free; bufX readers done
    prefetch32(smem + OFF_B, g_Bpk + 2 * 16384, tid);    // s1 chunk0 (overlaps epilogue)

    // epilogue 0: PE -> bufY; rel = k_n - q + PE -> bufX  (quad stores)
    #pragma unroll
    for (int pt = 0; pt < 2; ++pt) {
        float* acc = pt ? acc1 : acc0;
        char* xb = pt ? xb1 : xb0;
        char* yb = pt ? yb1 : yb0;
        const int nb0 = pt ? i10 : i00, nb1 = pt ? i11 : i01;
        const float* kr0 = g_k + (size_t)(bbase + nb0) * COUT;
        const float* kr1 = g_k + (size_t)(bbase + nb1) * COUT;
        const float* qr  = sQ + (2*q + pt) * 128;
        #pragma unroll
        for (int j = 0; j < 2; ++j) {
            float* a8 = acc + 8*j;
            frag_store_quad(yb, h, j, lane, a8);        // PE
            #pragma unroll
            for (int gg = 0; gg < 2; ++gg) {
                int c = 32*h + (2*j + gg)*8 + cl;
                float* a = a8 + gg*4;
                float2 q2 = *(const float2*)(qr + c);
                float2 k0 = *(const float2*)(kr0 + c);
                float2 k1 = *(const float2*)(kr1 + c);
                a[0] += k0.x - q2.x; a[1] += k0.y - q2.y;
                a[2] += k1.x - q2.x; a[3] += k1.y - q2.y;
            }
            frag_store_quad(xb, h, j, lane, a8);        // rel
        }
    }
    CP_WAIT_ALL(); __syncthreads();              // B = s1 chunk0; rel visible

    // ================= stage 1: mid = relu(rel @ Wa1 + ba1) ==================
    init_bias_h(acc0, ba1, h, lane); init_bias_h(acc1, ba1, h, lane);
    mma_pass_half(acc0, acc1, xb0, xb1, sB, h, lane, 0);
    __syncthreads();
    prefetch32(smem + OFF_B, g_Bpk + 3 * 16384, tid);    // s1 chunk1
    CP_WAIT_ALL(); __syncthreads();
    mma_pass_half(acc0, acc1, xb0, xb1, sB, h, lane, 1);
    __syncthreads();
    prefetch32(smem + OFF_B, g_Bpk + 4 * 16384, tid);    // s2 chunk0 (overlaps epilogue)

    // epilogue 1: relu -> mid frags (quad stores)
    #pragma unroll
    for (int pt = 0; pt < 2; ++pt) {
        float* acc = pt ? acc1 : acc0;
        char* xb = pt ? xb1 : xb0;
        #pragma unroll
        for (int j = 0; j < 2; ++j) {
            float a8[8];
            #pragma unroll
            for (int e = 0; e < 8; ++e) a8[e] = fmaxf(acc[8*j + e], 0.f);
            frag_store_quad(xb, h, j, lane, a8);
        }
    }
    CP_WAIT_ALL(); __syncthreads();              // B = s2 chunk0; mid visible

    // ================= stage 2: logits = mid @ Wa2 + ba2 =====================
    init_bias_h(acc0, ba2, h, lane); init_bias_h(acc1, ba2, h, lane);
    mma_pass_half(acc0, acc1, xb0, xb1, sB, h, lane, 0);
    __syncthreads();
    prefetch32(smem + OFF_B, g_Bpk + 5 * 16384, tid);    // s2 chunk1
    CP_WAIT_ALL(); __syncthreads();
    mma_pass_half(acc0, acc1, xb0, xb1, sB, h, lane, 1);

    // softmax over the 16 m-rows per channel + aggregate with (v_n + PE)
    // PE read: one LDS.128 (hi) + one (lo) per (pt, j) — conflict-free
    #pragma unroll
    for (int pt = 0; pt < 2; ++pt) {
        float* acc = pt ? acc1 : acc0;
        char* yb = pt ? yb1 : yb0;
        const int nb0 = pt ? i10 : i00, nb1 = pt ? i11 : i01;
        const float* vr0 = g_v + (size_t)(bbase + nb0) * COUT;
        const float* vr1 = g_v + (size_t)(bbase + nb1) * COUT;
        #pragma unroll
        for (int j = 0; j < 2; ++j) {
            int offb = (2*h + j) * 512 + lane * 16;
            uint4 Yh = *(const uint4*)(yb + offb);
            uint4 Yl = *(const uint4*)(yb + 4096 + offb);
            #pragma unroll
            for (int gg = 0; gg < 2; ++gg) {
                int g2 = 2*j + gg;
                int c = 32*h + g2*8 + cl;
                float* a = acc + g2*4;
                uint32_t h0 = gg ? Yh.z : Yh.x, h1 = gg ? Yh.w : Yh.y;
                uint32_t l0 = gg ? Yl.z : Yl.x, l1 = gg ? Yl.w : Yl.y;
                float me = fmaxf(a[0], a[2]), mo = fmaxf(a[1], a[3]);
                #pragma unroll
                for (int msk = 4; msk <= 16; msk <<= 1) {
                    me = fmaxf(me, __shfl_xor_sync(0xFFFFFFFFu, me, msk));
                    mo = fmaxf(mo, __shfl_xor_sync(0xFFFFFFFFu, mo, msk));
                }
                float e00 = __expf(a[0] - me), e10 = __expf(a[2] - me);
                float e01 = __expf(a[1] - mo), e11 = __expf(a[3] - mo);
                float pe0e = blo(h0) + blo(l0), pe0o = bhi(h0) + bhi(l0);
                float pe1e = blo(h1) + blo(l1), pe1o = bhi(h1) + bhi(l1);
                float2 v0 = *(const float2*)(vr0 + c);
                float2 v1 = *(const float2*)(vr1 + c);
                float nume = e00 * (v0.x + pe0e) + e10 * (v1.x + pe1e);
                float numo = e01 * (v0.y + pe0o) + e11 * (v1.y + pe1o);
                float dene = e00 + e10, deno = e01 + e11;
                #pragma unroll
                for (int msk = 4; msk <= 16; msk <<= 1) {
                    nume += __shfl_xor_sync(0xFFFFFFFFu, nume, msk);
                    numo += __shfl_xor_sync(0xFFFFFFFFu, numo, msk);
                    dene += __shfl_xor_sync(0xFFFFFFFFu, dene, msk);
                    deno += __shfl_xor_sync(0xFFFFFFFFu, deno, msk);
                }
                if (lane < 4) {
                    sAgg[(2*q + pt) * 128 + c]     = nume / dene;
                    sAgg[(2*q + pt) * 128 + c + 1] = numo / deno;
                }
            }
        }
    }
    __syncthreads();                             // sAgg complete; bufX free

    // Wo projection: split-K across 8 warps (16 k-rows each), partials in bufX
    {
        float* sPart = (float*)(smem + OFF_X);   // 8 warps x 4 pts x 128 cols = 16 KB
        const int c4 = 4 * lane;
        float4 pacc[4];
        #pragma unroll
        for (int p = 0; p < 4; ++p) pacc[p] = make_float4(0.f, 0.f, 0.f, 0.f);
        #pragma unroll
        for (int kk2 = 0; kk2 < 16; ++kk2) {
            int k = w * 16 + kk2;
            float4 wv = *reinterpret_cast<const float4*>(Wo + (size_t)k * 128 + c4);
            #pragma unroll
            for (int p = 0; p < 4; ++p) {
                float a = sAgg[p * 128 + k];
                pacc[p].x = fmaf(a, wv.x, pacc[p].x);
                pacc[p].y = fmaf(a, wv.y, pacc[p].y);
                pacc[p].z = fmaf(a, wv.z, pacc[p].z);
                pacc[p].w = fmaf(a, wv.w, pacc[p].w);
            }
        }
        #pragma unroll
        for (int p = 0; p < 4; ++p)
            *reinterpret_cast<float4*>(sPart + (size_t)(w * 4 + p) * 128 + c4) = pacc[p];
        __syncthreads();
        #pragma unroll
        for (int i = tid; i < 512; i += 256) {
            int p = i >> 7, c = i & 127;
            float sum = bo[c];
            #pragma unroll
            for (int ww = 0; ww < 8; ++ww) sum += sPart[(size_t)(ww * 4 + p) * 128 + c];
            out[(size_t)(p0 + p) * COUT + c] = sum;
        }
    }
}

// ---------------------------------------------------------------------------
extern "C" void kernel_launch(void* const* d_in, const int* in_sizes, int n_in,
                              void* d_out, int out_size)
{
    const float* x   = (const float*)d_in[0];
    const float* pos = (const float*)d_in[1];
    const int*   idx = (const int*)  d_in[2];
    const float* Wq  = (const float*)d_in[3];
    const float* bq  = (const float*)d_in[4];
    const float* Wkv = (const float*)d_in[5];
    const float* bkv = (const float*)d_in[6];
    const float* Wp1 = (const float*)d_in[7];
    const float* bp1 = (const float*)d_in[8];
    const float* Wp2 = (const float*)d_in[9];
    const float* bp2 = (const float*)d_in[10];
    const float* Wa1 = (const float*)d_in[11];
    const float* ba1 = (const float*)d_in[12];
    const float* Wa2 = (const float*)d_in[13];
    const float* ba2 = (const float*)d_in[14];
    const float* Wo  = (const float*)d_in[15];
    const float* bo  = (const float*)d_in[16];
    float* out = (float*)d_out;

    cudaFuncSetAttribute(attn_kernel, cudaFuncAttributeMaxDynamicSharedMemorySize, SMEM_TOTAL);

    prep_kernel<<<384 + 3 * 512, 256>>>(x, Wq, bq, Wkv, bkv, Wp2, Wa1, Wa2);
    attn_kernel<<<NPTS / 4, 256, SMEM_TOTAL>>>(pos, idx, Wp1, bp1, bp2, ba1, ba2, Wo, bo, out);
}